// round 13
// baseline (speedup 1.0000x reference)
#include <cuda_runtime.h>

#define BETA  0.95f
#define PI_F  3.141592653589793f
#define BB    32
#define NN    1024

// Scratch (device globals — no allocation allowed)
__device__ float g_spk0[BB * NN];
__device__ float g_a0[BB * NN];
__device__ float g_t0[BB * NN];
__device__ float g_a1[BB * NN];
__device__ float g_t1[BB * NN];
__device__ float g_mean[2 * BB];
__device__ float g_part[2 * BB * 128 * 2];   // per-(layer,b,htile) {spk*prev, spk}
__device__ int   g_flag;                     // compute1 completion counter

// ---------------------------------------------------------------------------
// K1: layer-0 compute only (GEMM 8h x 4b -> LIF -> a0/t0 scratch) + means
// + flag reset.
// ---------------------------------------------------------------------------
__global__ void __launch_bounds__(256)
k1_compute0(const float* __restrict__ x,
            const float* __restrict__ W,
            const float* __restrict__ mem_in,
            const float* __restrict__ ps0,
            const float* __restrict__ ps1,
            const float* __restrict__ itr,
            const int*   __restrict__ bf_ptr,
            float* __restrict__ mem_out)
{
    const int tid = threadIdx.x;
    const int w   = tid >> 5, lane = tid & 31;
    const int bid = blockIdx.x;

    if (bid >= 1024) {                      // row means of ps0 / ps1 + reset
        const int l = bid - 1024;
        if (l == 0 && tid == 0) g_flag = 0;
        const float* prev = l ? ps1 : ps0;
        #pragma unroll
        for (int r = 0; r < 4; r++) {
            const int b = w * 4 + r;
            const float* row = prev + (size_t)b * NN;
            float s = 0.f;
            #pragma unroll
            for (int k = 0; k < NN / 32; k++) s += row[lane + 32 * k];
            #pragma unroll
            for (int o = 16; o; o >>= 1) s += __shfl_down_sync(0xffffffffu, s, o);
            if (lane == 0) g_mean[l * BB + b] = s * (1.0f / NN);
        }
        return;
    }

    __shared__ __align__(16) float xs[4][NN];
    __shared__ float redc[8][4][2];

    const int ht = bid >> 3;
    const int b0 = (bid & 7) * 4;

    {
        const float4* xp = (const float4*)(x + (size_t)b0 * NN);
        float4 xv[4];
        #pragma unroll
        for (int r = 0; r < 4; r++) xv[r] = __ldg(xp + tid + 256 * r);
        float4* xsp = (float4*)xs;
        #pragma unroll
        for (int r = 0; r < 4; r++) xsp[tid + 256 * r] = xv[r];
        if (ht == 0) {
            const float4* ip = (const float4*)(itr + (size_t)b0 * NN);
            float4* tp = (float4*)(g_t0 + (size_t)b0 * NN);
            #pragma unroll
            for (int r = 0; r < 4; r++) {
                float4 iv = __ldg(ip + tid + 256 * r);
                float4 t;
                t.x = fmaf(BETA, iv.x, xv[r].x);
                t.y = fmaf(BETA, iv.y, xv[r].y);
                t.z = fmaf(BETA, iv.z, xv[r].z);
                t.w = fmaf(BETA, iv.w, xv[r].w);
                tp[tid + 256 * r] = t;
            }
        }
    }
    __syncthreads();

    const int h = ht * 8 + w;
    const float4* wr = (const float4*)(W + (size_t)h * NN);
    float4 wv[8];
    #pragma unroll
    for (int i = 0; i < 8; i++) wv[i] = __ldg(wr + i * 32 + lane);

    const float4* x0p = (const float4*)xs[0];
    const float4* x1p = (const float4*)xs[1];
    const float4* x2p = (const float4*)xs[2];
    const float4* x3p = (const float4*)xs[3];
    float acc0 = 0.f, acc1 = 0.f, acc2 = 0.f, acc3 = 0.f;
    #pragma unroll
    for (int i = 0; i < 8; i++) {
        const int o = i * 32 + lane;
        const float4 wvv = wv[i];
        float4 v;
        v = x0p[o];
        acc0 = fmaf(wvv.x, v.x, fmaf(wvv.y, v.y, fmaf(wvv.z, v.z, fmaf(wvv.w, v.w, acc0))));
        v = x1p[o];
        acc1 = fmaf(wvv.x, v.x, fmaf(wvv.y, v.y, fmaf(wvv.z, v.z, fmaf(wvv.w, v.w, acc1))));
        v = x2p[o];
        acc2 = fmaf(wvv.x, v.x, fmaf(wvv.y, v.y, fmaf(wvv.z, v.z, fmaf(wvv.w, v.w, acc2))));
        v = x3p[o];
        acc3 = fmaf(wvv.x, v.x, fmaf(wvv.y, v.y, fmaf(wvv.z, v.z, fmaf(wvv.w, v.w, acc3))));
    }
    #pragma unroll
    for (int o = 16; o; o >>= 1) {
        acc0 += __shfl_xor_sync(0xffffffffu, acc0, o);
        acc1 += __shfl_xor_sync(0xffffffffu, acc1, o);
        acc2 += __shfl_xor_sync(0xffffffffu, acc2, o);
        acc3 += __shfl_xor_sync(0xffffffffu, acc3, o);
    }

    if (lane < 4) {
        float dot = (lane == 0) ? acc0 : (lane == 1) ? acc1
                  : (lane == 2) ? acc2 : acc3;
        const int idx = (b0 + lane) * NN + h;
        float m = BETA * mem_in[idx] + dot;
        float s = (m > 1.0f) ? 1.0f : 0.0f;
        m -= s;
        mem_out[idx] = m;
        g_spk0[idx] = s;

        float pv  = ps0[idx];
        float u   = PI_F * (m - 1.0f);
        float sur = 1.0f / (PI_F * (1.0f + u * u));
        g_a0[idx] = ((float)(*bf_ptr)) * pv * sur;

        redc[w][lane][0] = s * pv;
        redc[w][lane][1] = s;
    }
    __syncthreads();
    if (tid < 8) {
        const int bb = tid >> 1, comp = tid & 1;
        float sum = 0.f;
        #pragma unroll
        for (int ww = 0; ww < 8; ww++) sum += redc[ww][bb][comp];
        g_part[((b0 + bb) * 128 + ht) * 2 + comp] = sum;
    }
}

// ---------------------------------------------------------------------------
// Pure store of one 64-row x 1024-col dW tile (256 thr, streaming stores).
// ---------------------------------------------------------------------------
__device__ __forceinline__ void store_tile64(
    const float* __restrict__ a_base, const float* __restrict__ t_base,
    float* __restrict__ dW, int sid)
{
    __shared__ float as_[64];
    const int tid  = threadIdx.x;
    const int b    = sid >> 4;
    const int tile = sid & 15;
    const float*  a = a_base + b * NN + tile * 64;
    const float2* t = (const float2*)(t_base + b * NN);
    if (tid < 64) as_[tid] = a[tid];
    const float2 t0 = __ldg(t + tid);
    const float2 t1 = __ldg(t + tid + 256);
    __syncthreads();

    float* dst = dW + (size_t)b * NN * NN + (size_t)tile * 64 * NN;
    #pragma unroll 4
    for (int i = 0; i < 64; i++) {
        const float av = as_[i];
        float* row = dst + (size_t)i * NN;
        float2 v0, v1;
        v0.x = av * t0.x; v0.y = av * t0.y;
        v1.x = av * t1.x; v1.y = av * t1.y;
        __stcs((float2*)row + tid,       v0);
        __stcs((float2*)row + tid + 256, v1);
    }
}

// ---------------------------------------------------------------------------
// K2: everything after layer-0 compute, one launch.
//   bids    0..511  : pure dW0 store tiles (DRAM busy from t=0)
//   bids  512..1535 : layer-1 compute (signals g_flag on completion)
//   bids 1536..2047 : dW1 store tiles (spin until compute1 complete)
//   bids 2048..2049 : loss finalize (spin)
// Spinner population (514) < resident capacity -> deadlock-free.
// ---------------------------------------------------------------------------
__global__ void __launch_bounds__(256)
k2_all(const float* __restrict__ W1, const float* __restrict__ mem1,
       const float* __restrict__ ps1, const float* __restrict__ it1,
       const int* __restrict__ bf_ptr,
       float* __restrict__ mem1_o, float* __restrict__ spk1_o,
       float* __restrict__ dW0, float* __restrict__ dW1,
       float* __restrict__ loss_o)
{
    const int bid = blockIdx.x;
    const int tid = threadIdx.x;

    if (bid < 512) {                        // ---- dW0 pure store ----
        store_tile64(g_a0, g_t0, dW0, bid);
        return;
    }

    if (bid < 1536) {                       // ---- layer-1 compute ----
        __shared__ __align__(16) float xs[4][NN];
        __shared__ float redc[8][4][2];

        const int cid = bid - 512;
        const int w   = tid >> 5, lane = tid & 31;
        const int ht  = cid >> 3;
        const int b0  = (cid & 7) * 4;

        {
            const float4* xp = (const float4*)(g_spk0 + (size_t)b0 * NN);
            float4 xv[4];
            #pragma unroll
            for (int r = 0; r < 4; r++) xv[r] = __ldg(xp + tid + 256 * r);
            float4* xsp = (float4*)xs;
            #pragma unroll
            for (int r = 0; r < 4; r++) xsp[tid + 256 * r] = xv[r];
            if (ht == 0) {
                const float4* ip = (const float4*)(it1 + (size_t)b0 * NN);
                float4* tp = (float4*)(g_t1 + (size_t)b0 * NN);
                #pragma unroll
                for (int r = 0; r < 4; r++) {
                    float4 iv = __ldg(ip + tid + 256 * r);
                    float4 t;
                    t.x = fmaf(BETA, iv.x, xv[r].x);
                    t.y = fmaf(BETA, iv.y, xv[r].y);
                    t.z = fmaf(BETA, iv.z, xv[r].z);
                    t.w = fmaf(BETA, iv.w, xv[r].w);
                    tp[tid + 256 * r] = t;
                }
            }
        }
        __syncthreads();

        const int h = ht * 8 + w;
        const float4* wr = (const float4*)(W1 + (size_t)h * NN);
        float4 wv[8];
        #pragma unroll
        for (int i = 0; i < 8; i++) wv[i] = __ldg(wr + i * 32 + lane);

        const float4* x0p = (const float4*)xs[0];
        const float4* x1p = (const float4*)xs[1];
        const float4* x2p = (const float4*)xs[2];
        const float4* x3p = (const float4*)xs[3];
        float acc0 = 0.f, acc1 = 0.f, acc2 = 0.f, acc3 = 0.f;
        #pragma unroll
        for (int i = 0; i < 8; i++) {
            const int o = i * 32 + lane;
            const float4 wvv = wv[i];
            float4 v;
            v = x0p[o];
            acc0 = fmaf(wvv.x, v.x, fmaf(wvv.y, v.y, fmaf(wvv.z, v.z, fmaf(wvv.w, v.w, acc0))));
            v = x1p[o];
            acc1 = fmaf(wvv.x, v.x, fmaf(wvv.y, v.y, fmaf(wvv.z, v.z, fmaf(wvv.w, v.w, acc1))));
            v = x2p[o];
            acc2 = fmaf(wvv.x, v.x, fmaf(wvv.y, v.y, fmaf(wvv.z, v.z, fmaf(wvv.w, v.w, acc2))));
            v = x3p[o];
            acc3 = fmaf(wvv.x, v.x, fmaf(wvv.y, v.y, fmaf(wvv.z, v.z, fmaf(wvv.w, v.w, acc3))));
        }
        #pragma unroll
        for (int o = 16; o; o >>= 1) {
            acc0 += __shfl_xor_sync(0xffffffffu, acc0, o);
            acc1 += __shfl_xor_sync(0xffffffffu, acc1, o);
            acc2 += __shfl_xor_sync(0xffffffffu, acc2, o);
            acc3 += __shfl_xor_sync(0xffffffffu, acc3, o);
        }

        if (lane < 4) {
            float dot = (lane == 0) ? acc0 : (lane == 1) ? acc1
                      : (lane == 2) ? acc2 : acc3;
            const int idx = (b0 + lane) * NN + h;
            float m = BETA * mem1[idx] + dot;
            float s = (m > 1.0f) ? 1.0f : 0.0f;
            m -= s;
            mem1_o[idx] = m;
            spk1_o[idx] = s;

            float pv  = ps1[idx];
            float u   = PI_F * (m - 1.0f);
            float sur = 1.0f / (PI_F * (1.0f + u * u));
            g_a1[idx] = ((float)(*bf_ptr)) * pv * sur;

            redc[w][lane][0] = s * pv;
            redc[w][lane][1] = s;
        }
        __syncthreads();
        if (tid < 8) {
            const int bb = tid >> 1, comp = tid & 1;
            float sum = 0.f;
            #pragma unroll
            for (int ww = 0; ww < 8; ww++) sum += redc[ww][bb][comp];
            g_part[BB * 128 * 2 + ((b0 + bb) * 128 + ht) * 2 + comp] = sum;
        }
        // release: all writes visible, then signal
        __threadfence();
        __syncthreads();
        if (tid == 0) atomicAdd(&g_flag, 1);
        return;
    }

    // ---- spin until all 1024 compute1 blocks have signalled ----
    if (tid == 0) {
        volatile int* f = &g_flag;
        while (*f < 1024) __nanosleep(256);
    }
    __syncthreads();
    __threadfence();

    if (bid < 2048) {                       // ---- dW1 pure store ----
        store_tile64(g_a1, g_t1, dW1, bid - 1536);
        return;
    }

    // ---- loss finalize for layer l ----
    {
        __shared__ float vsh[BB];
        const int l = bid - 2048;
        const float* part = g_part + l * (BB * 128 * 2);
        const int b = tid >> 3, seg = tid & 7;
        float s1 = 0.f, s2 = 0.f;
        for (int h2 = seg * 16; h2 < seg * 16 + 16; h2++) {
            s1 += part[(b * 128 + h2) * 2 + 0];
            s2 += part[(b * 128 + h2) * 2 + 1];
        }
        #pragma unroll
        for (int o = 4; o; o >>= 1) {
            s1 += __shfl_down_sync(0xffffffffu, s1, o);
            s2 += __shfl_down_sync(0xffffffffu, s2, o);
        }
        if (seg == 0) vsh[b] = s1 - g_mean[l * BB + b] * s2;
        __syncthreads();
        if (tid == 0) {
            float tot = 0.f;
            #pragma unroll
            for (int i = 0; i < BB; i++) tot += vsh[i];
            loss_o[l] = -((float)(*bf_ptr)) * tot * (1.0f / (float)BB);
        }
    }
}

extern "C" void kernel_launch(void* const* d_in, const int* in_sizes, int n_in,
                              void* d_out, int out_size) {
    (void)in_sizes; (void)n_in; (void)out_size;
    const float* inp  = (const float*)d_in[0];
    const float* W0   = (const float*)d_in[1];
    const float* W1   = (const float*)d_in[2];
    const float* mem0 = (const float*)d_in[3];
    const float* mem1 = (const float*)d_in[4];
    const float* ps0  = (const float*)d_in[5];
    const float* ps1  = (const float*)d_in[6];
    const float* it0  = (const float*)d_in[7];
    const float* it1  = (const float*)d_in[8];
    const int*   bf   = (const int*)d_in[9];

    float* out    = (float*)d_out;
    float* spk1_o = out;                               // (32,1024)
    float* mem0_o = out + BB * NN;                     // (32,1024)
    float* mem1_o = out + 2 * BB * NN;                 // (32,1024)
    float* loss_o = out + 3 * BB * NN;                 // (2,)
    float* dW0_o  = out + 3 * BB * NN + 2;             // (32,1024,1024)
    float* dW1_o  = dW0_o + (size_t)BB * NN * NN;      // (32,1024,1024)

    k1_compute0<<<1026, 256>>>(inp, W0, mem0, ps0, ps1, it0, bf, mem0_o);
    k2_all<<<2050, 256>>>(W1, mem1, ps1, it1, bf,
                          mem1_o, spk1_o, dW0_o, dW1_o, loss_o);
}

// round 14
// speedup vs baseline: 1.0877x; 1.0877x over previous
#include <cuda_runtime.h>

#define BETA  0.95f
#define PI_F  3.141592653589793f
#define BB    32
#define NN    1024

// Scratch (device globals — no allocation allowed)
__device__ float g_spk0[BB * NN];
__device__ float g_a0[BB * NN];
__device__ float g_t0[BB * NN];
__device__ float g_mean[2 * BB];
__device__ float g_part[2 * BB * 128 * 2];   // per-(layer,b,htile) {spk*prev, spk}

// ---------------------------------------------------------------------------
// K1: layer-0 compute only. W prefetched BEFORE x staging so its latency
// hides under the stage+sync phase. grid 1026 (1024 compute + 2 means).
// ---------------------------------------------------------------------------
__global__ void __launch_bounds__(256)
k1_compute0(const float* __restrict__ x,
            const float* __restrict__ W,
            const float* __restrict__ mem_in,
            const float* __restrict__ ps0,
            const float* __restrict__ ps1,
            const float* __restrict__ itr,
            const int*   __restrict__ bf_ptr,
            float* __restrict__ mem_out)
{
    const int tid = threadIdx.x;
    const int w   = tid >> 5, lane = tid & 31;
    const int bid = blockIdx.x;

    if (bid >= 1024) {                      // row means of ps0 / ps1
        const int l = bid - 1024;
        const float* prev = l ? ps1 : ps0;
        #pragma unroll
        for (int r = 0; r < 4; r++) {
            const int b = w * 4 + r;
            const float* row = prev + (size_t)b * NN;
            float s = 0.f;
            #pragma unroll
            for (int k = 0; k < NN / 32; k++) s += row[lane + 32 * k];
            #pragma unroll
            for (int o = 16; o; o >>= 1) s += __shfl_down_sync(0xffffffffu, s, o);
            if (lane == 0) g_mean[l * BB + b] = s * (1.0f / NN);
        }
        return;
    }

    __shared__ __align__(16) float xs[4][NN];
    __shared__ float redc[8][4][2];

    const int ht = bid >> 3;
    const int b0 = (bid & 7) * 4;

    // ---- W prefetch FIRST (latency overlaps the staging below) ----
    const int h = ht * 8 + w;
    const float4* wr = (const float4*)(W + (size_t)h * NN);
    float4 wv[8];
    #pragma unroll
    for (int i = 0; i < 8; i++) wv[i] = __ldg(wr + i * 32 + lane);

    // ---- stage x; ht==0 blocks also emit trace t0 ----
    {
        const float4* xp = (const float4*)(x + (size_t)b0 * NN);
        float4 xv[4];
        #pragma unroll
        for (int r = 0; r < 4; r++) xv[r] = __ldg(xp + tid + 256 * r);
        float4* xsp = (float4*)xs;
        #pragma unroll
        for (int r = 0; r < 4; r++) xsp[tid + 256 * r] = xv[r];
        if (ht == 0) {
            const float4* ip = (const float4*)(itr + (size_t)b0 * NN);
            float4* tp = (float4*)(g_t0 + (size_t)b0 * NN);
            #pragma unroll
            for (int r = 0; r < 4; r++) {
                float4 iv = __ldg(ip + tid + 256 * r);
                float4 t;
                t.x = fmaf(BETA, iv.x, xv[r].x);
                t.y = fmaf(BETA, iv.y, xv[r].y);
                t.z = fmaf(BETA, iv.z, xv[r].z);
                t.w = fmaf(BETA, iv.w, xv[r].w);
                tp[tid + 256 * r] = t;
            }
        }
    }
    __syncthreads();

    const float4* x0p = (const float4*)xs[0];
    const float4* x1p = (const float4*)xs[1];
    const float4* x2p = (const float4*)xs[2];
    const float4* x3p = (const float4*)xs[3];
    float acc0 = 0.f, acc1 = 0.f, acc2 = 0.f, acc3 = 0.f;
    #pragma unroll
    for (int i = 0; i < 8; i++) {
        const int o = i * 32 + lane;
        const float4 wvv = wv[i];
        float4 v;
        v = x0p[o];
        acc0 = fmaf(wvv.x, v.x, fmaf(wvv.y, v.y, fmaf(wvv.z, v.z, fmaf(wvv.w, v.w, acc0))));
        v = x1p[o];
        acc1 = fmaf(wvv.x, v.x, fmaf(wvv.y, v.y, fmaf(wvv.z, v.z, fmaf(wvv.w, v.w, acc1))));
        v = x2p[o];
        acc2 = fmaf(wvv.x, v.x, fmaf(wvv.y, v.y, fmaf(wvv.z, v.z, fmaf(wvv.w, v.w, acc2))));
        v = x3p[o];
        acc3 = fmaf(wvv.x, v.x, fmaf(wvv.y, v.y, fmaf(wvv.z, v.z, fmaf(wvv.w, v.w, acc3))));
    }
    #pragma unroll
    for (int o = 16; o; o >>= 1) {
        acc0 += __shfl_xor_sync(0xffffffffu, acc0, o);
        acc1 += __shfl_xor_sync(0xffffffffu, acc1, o);
        acc2 += __shfl_xor_sync(0xffffffffu, acc2, o);
        acc3 += __shfl_xor_sync(0xffffffffu, acc3, o);
    }

    if (lane < 4) {
        float dot = (lane == 0) ? acc0 : (lane == 1) ? acc1
                  : (lane == 2) ? acc2 : acc3;
        const int idx = (b0 + lane) * NN + h;
        float m = BETA * mem_in[idx] + dot;
        float s = (m > 1.0f) ? 1.0f : 0.0f;
        m -= s;
        mem_out[idx] = m;
        g_spk0[idx] = s;

        float pv  = ps0[idx];
        float u   = PI_F * (m - 1.0f);
        float sur = 1.0f / (PI_F * (1.0f + u * u));
        g_a0[idx] = ((float)(*bf_ptr)) * pv * sur;

        redc[w][lane][0] = s * pv;
        redc[w][lane][1] = s;
    }
    __syncthreads();
    if (tid < 8) {
        const int bb = tid >> 1, comp = tid & 1;
        float sum = 0.f;
        #pragma unroll
        for (int ww = 0; ww < 8; ww++) sum += redc[ww][bb][comp];
        g_part[((b0 + bb) * 128 + ht) * 2 + comp] = sum;
    }
}

// ---------------------------------------------------------------------------
// K2: uniform fused blocks, GEMM interleaved INTO the dW0 store loop so the
// DRAM write stream never pauses for compute. 1024 blocks x 256 threads.
// ---------------------------------------------------------------------------
__global__ void __launch_bounds__(256)
k2_mid(const float* __restrict__ W1, const float* __restrict__ mem1,
       const float* __restrict__ ps1, const float* __restrict__ it1,
       const int* __restrict__ bf_ptr,
       float* __restrict__ mem1_o, float* __restrict__ spk1_o,
       float* __restrict__ dW0, float* __restrict__ dW1)
{
    __shared__ __align__(16) float xs[4][NN];   // spk0 rows
    __shared__ __align__(16) float ts[4][NN];   // trace1 rows
    __shared__ float a0sh[32];                  // a0[w2*4+bb]
    __shared__ float a1sh[8][4];
    __shared__ float redc[8][4][2];

    const int tid = threadIdx.x;
    const int w   = tid >> 5, lane = tid & 31;
    const int cid = blockIdx.x;
    const int ht  = cid >> 3;
    const int b0  = (cid & 7) * 4;

    // ---- stage: spk0 + trace1 -> smem ; a0 tile -> smem ----
    {
        const float4* xp = (const float4*)(g_spk0 + (size_t)b0 * NN);
        const float4* ip = (const float4*)(it1    + (size_t)b0 * NN);
        float4 xv[4], iv[4];
        #pragma unroll
        for (int r = 0; r < 4; r++) {
            xv[r] = __ldg(xp + tid + 256 * r);
            iv[r] = __ldg(ip + tid + 256 * r);
        }
        if (tid < 32)
            a0sh[tid] = g_a0[(size_t)(b0 + (tid & 3)) * NN + ht * 8 + (tid >> 2)];
        float4* xsp = (float4*)xs;
        float4* tsp = (float4*)ts;
        #pragma unroll
        for (int r = 0; r < 4; r++) {
            xsp[tid + 256 * r] = xv[r];
            float4 t;
            t.x = fmaf(BETA, iv[r].x, xv[r].x);
            t.y = fmaf(BETA, iv[r].y, xv[r].y);
            t.z = fmaf(BETA, iv[r].z, xv[r].z);
            t.w = fmaf(BETA, iv[r].w, xv[r].w);
            tsp[tid + 256 * r] = t;
        }
    }
    __syncthreads();

    // ---- W1 front-batch (in flight during first store iterations) ----
    const int h = ht * 8 + w;
    const float4* wr = (const float4*)(W1 + (size_t)h * NN);
    float4 wv[8];
    #pragma unroll
    for (int i = 0; i < 8; i++) wv[i] = __ldg(wr + i * 32 + lane);

    const float4* x0p = (const float4*)xs[0];
    const float4* x1p = (const float4*)xs[1];
    const float4* x2p = (const float4*)xs[2];
    const float4* x3p = (const float4*)xs[3];
    float acc0 = 0.f, acc1 = 0.f, acc2 = 0.f, acc3 = 0.f;

    // ---- dW0 store loop with GEMM interleaved (chunks in iterations 0..7
    //      of the flattened (bb,w2) loop) ----
    #pragma unroll
    for (int bb = 0; bb < 4; bb++) {
        const float2* t0 = (const float2*)(g_t0 + (size_t)(b0 + bb) * NN);
        const float2 t0A = __ldg(t0 + tid);
        const float2 t0B = __ldg(t0 + tid + 256);
        float* brow = dW0 + (size_t)(b0 + bb) * NN * NN + (size_t)(ht * 8) * NN;
        #pragma unroll
        for (int w2 = 0; w2 < 8; w2++) {
            const float av = a0sh[w2 * 4 + bb];
            float* row = brow + (size_t)w2 * NN;
            float2 v0, v1;
            v0.x = av * t0A.x; v0.y = av * t0A.y;
            v1.x = av * t0B.x; v1.y = av * t0B.y;
            __stcs((float2*)row + tid,       v0);
            __stcs((float2*)row + tid + 256, v1);

            if (bb == 0) {                  // GEMM chunk w2 (compile-time)
                const int o = w2 * 32 + lane;
                const float4 wvv = wv[w2];
                float4 v;
                v = x0p[o];
                acc0 = fmaf(wvv.x, v.x, fmaf(wvv.y, v.y, fmaf(wvv.z, v.z, fmaf(wvv.w, v.w, acc0))));
                v = x1p[o];
                acc1 = fmaf(wvv.x, v.x, fmaf(wvv.y, v.y, fmaf(wvv.z, v.z, fmaf(wvv.w, v.w, acc1))));
                v = x2p[o];
                acc2 = fmaf(wvv.x, v.x, fmaf(wvv.y, v.y, fmaf(wvv.z, v.z, fmaf(wvv.w, v.w, acc2))));
                v = x3p[o];
                acc3 = fmaf(wvv.x, v.x, fmaf(wvv.y, v.y, fmaf(wvv.z, v.z, fmaf(wvv.w, v.w, acc3))));
            }
        }
    }

    #pragma unroll
    for (int o = 16; o; o >>= 1) {
        acc0 += __shfl_xor_sync(0xffffffffu, acc0, o);
        acc1 += __shfl_xor_sync(0xffffffffu, acc1, o);
        acc2 += __shfl_xor_sync(0xffffffffu, acc2, o);
        acc3 += __shfl_xor_sync(0xffffffffu, acc3, o);
    }

    // ---- LIF epilogue ----
    if (lane < 4) {
        float dot = (lane == 0) ? acc0 : (lane == 1) ? acc1
                  : (lane == 2) ? acc2 : acc3;
        const int idx = (b0 + lane) * NN + h;
        float m = BETA * mem1[idx] + dot;
        float s = (m > 1.0f) ? 1.0f : 0.0f;
        m -= s;
        mem1_o[idx] = m;
        spk1_o[idx] = s;

        float pv  = ps1[idx];
        float u   = PI_F * (m - 1.0f);
        float sur = 1.0f / (PI_F * (1.0f + u * u));
        a1sh[w][lane] = ((float)(*bf_ptr)) * pv * sur;

        redc[w][lane][0] = s * pv;
        redc[w][lane][1] = s;
    }
    __syncthreads();

    if (tid < 8) {
        const int bb = tid >> 1, comp = tid & 1;
        float sum = 0.f;
        #pragma unroll
        for (int ww = 0; ww < 8; ww++) sum += redc[ww][bb][comp];
        g_part[BB * 128 * 2 + ((b0 + bb) * 128 + ht) * 2 + comp] = sum;
    }

    // ---- dW1 store (trace pairs from smem) ----
    #pragma unroll
    for (int bb = 0; bb < 4; bb++) {
        const float2 tA = *((const float2*)ts[bb] + tid);
        const float2 tB = *((const float2*)ts[bb] + tid + 256);
        float* brow = dW1 + (size_t)(b0 + bb) * NN * NN + (size_t)(ht * 8) * NN;
        #pragma unroll
        for (int w2 = 0; w2 < 8; w2++) {
            const float av = a1sh[w2][bb];
            float* row = brow + (size_t)w2 * NN;
            float2 v0, v1;
            v0.x = av * tA.x; v0.y = av * tA.y;
            v1.x = av * tB.x; v1.y = av * tB.y;
            __stcs((float2*)row + tid,       v0);
            __stcs((float2*)row + tid + 256, v1);
        }
    }
}

// ---------------------------------------------------------------------------
// K3: loss finalize, 1 block 256 threads.
// ---------------------------------------------------------------------------
__global__ void __launch_bounds__(256)
k3_loss(const int* __restrict__ bf, float* __restrict__ loss_o)
{
    __shared__ float vsh[64];
    const int tid  = threadIdx.x;
    const int pair = tid >> 2;            // 0..63 = (l,b)
    const int seg  = tid & 3;
    const int l = pair >> 5, b = pair & 31;
    const float* part = g_part + l * (BB * 128 * 2) + b * 128 * 2;
    float s1 = 0.f, s2 = 0.f;
    for (int h2 = seg * 32; h2 < seg * 32 + 32; h2++) {
        s1 += part[h2 * 2 + 0];
        s2 += part[h2 * 2 + 1];
    }
    #pragma unroll
    for (int o = 2; o; o >>= 1) {
        s1 += __shfl_down_sync(0xffffffffu, s1, o);
        s2 += __shfl_down_sync(0xffffffffu, s2, o);
    }
    if (seg == 0) vsh[pair] = s1 - g_mean[l * BB + b] * s2;
    __syncthreads();
    if (tid < 2) {
        float tot = 0.f;
        #pragma unroll
        for (int i = 0; i < BB; i++) tot += vsh[tid * BB + i];
        loss_o[tid] = -((float)(*bf)) * tot * (1.0f / (float)BB);
    }
}

extern "C" void kernel_launch(void* const* d_in, const int* in_sizes, int n_in,
                              void* d_out, int out_size) {
    (void)in_sizes; (void)n_in; (void)out_size;
    const float* inp  = (const float*)d_in[0];
    const float* W0   = (const float*)d_in[1];
    const float* W1   = (const float*)d_in[2];
    const float* mem0 = (const float*)d_in[3];
    const float* mem1 = (const float*)d_in[4];
    const float* ps0  = (const float*)d_in[5];
    const float* ps1  = (const float*)d_in[6];
    const float* it0  = (const float*)d_in[7];
    const float* it1  = (const float*)d_in[8];
    const int*   bf   = (const int*)d_in[9];

    float* out    = (float*)d_out;
    float* spk1_o = out;                               // (32,1024)
    float* mem0_o = out + BB * NN;                     // (32,1024)
    float* mem1_o = out + 2 * BB * NN;                 // (32,1024)
    float* loss_o = out + 3 * BB * NN;                 // (2,)
    float* dW0_o  = out + 3 * BB * NN + 2;             // (32,1024,1024)
    float* dW1_o  = dW0_o + (size_t)BB * NN * NN;      // (32,1024,1024)

    k1_compute0<<<1026, 256>>>(inp, W0, mem0, ps0, ps1, it0, bf, mem0_o);
    k2_mid<<<1024, 256>>>(W1, mem1, ps1, it1, bf,
                          mem1_o, spk1_o, dW0_o, dW1_o);
    k3_loss<<<1, 256>>>(bf, loss_o);
}

// round 15
// speedup vs baseline: 1.1260x; 1.0351x over previous
#include <cuda_runtime.h>

#define BETA  0.95f
#define PI_F  3.141592653589793f
#define BB    32
#define NN    1024

// Scratch (device globals — no allocation allowed)
__device__ float g_spk0[BB * NN];
__device__ float g_a0[BB * NN];
__device__ float g_t0[BB * NN];
__device__ float g_mean[2 * BB];
__device__ float g_part[2 * BB * 128 * 2];   // per-(layer,b,htile) {spk*prev, spk}

// ---------------------------------------------------------------------------
// K1: layer-0 compute only (R12 version — 50 regs, x staged after no W
// prefetch). grid 1026 (1024 compute + 2 means).
// ---------------------------------------------------------------------------
__global__ void __launch_bounds__(256)
k1_compute0(const float* __restrict__ x,
            const float* __restrict__ W,
            const float* __restrict__ mem_in,
            const float* __restrict__ ps0,
            const float* __restrict__ ps1,
            const float* __restrict__ itr,
            const int*   __restrict__ bf_ptr,
            float* __restrict__ mem_out)
{
    const int tid = threadIdx.x;
    const int w   = tid >> 5, lane = tid & 31;
    const int bid = blockIdx.x;

    if (bid >= 1024) {                      // row means of ps0 / ps1
        const int l = bid - 1024;
        const float* prev = l ? ps1 : ps0;
        #pragma unroll
        for (int r = 0; r < 4; r++) {
            const int b = w * 4 + r;
            const float* row = prev + (size_t)b * NN;
            float s = 0.f;
            #pragma unroll
            for (int k = 0; k < NN / 32; k++) s += row[lane + 32 * k];
            #pragma unroll
            for (int o = 16; o; o >>= 1) s += __shfl_down_sync(0xffffffffu, s, o);
            if (lane == 0) g_mean[l * BB + b] = s * (1.0f / NN);
        }
        return;
    }

    __shared__ __align__(16) float xs[4][NN];
    __shared__ float redc[8][4][2];

    const int ht = bid >> 3;
    const int b0 = (bid & 7) * 4;

    {
        const float4* xp = (const float4*)(x + (size_t)b0 * NN);
        float4 xv[4];
        #pragma unroll
        for (int r = 0; r < 4; r++) xv[r] = __ldg(xp + tid + 256 * r);
        float4* xsp = (float4*)xs;
        #pragma unroll
        for (int r = 0; r < 4; r++) xsp[tid + 256 * r] = xv[r];
        if (ht == 0) {
            const float4* ip = (const float4*)(itr + (size_t)b0 * NN);
            float4* tp = (float4*)(g_t0 + (size_t)b0 * NN);
            #pragma unroll
            for (int r = 0; r < 4; r++) {
                float4 iv = __ldg(ip + tid + 256 * r);
                float4 t;
                t.x = fmaf(BETA, iv.x, xv[r].x);
                t.y = fmaf(BETA, iv.y, xv[r].y);
                t.z = fmaf(BETA, iv.z, xv[r].z);
                t.w = fmaf(BETA, iv.w, xv[r].w);
                tp[tid + 256 * r] = t;
            }
        }
    }
    __syncthreads();

    const int h = ht * 8 + w;
    const float4* wr = (const float4*)(W + (size_t)h * NN);
    float4 wv[8];
    #pragma unroll
    for (int i = 0; i < 8; i++) wv[i] = __ldg(wr + i * 32 + lane);

    const float4* x0p = (const float4*)xs[0];
    const float4* x1p = (const float4*)xs[1];
    const float4* x2p = (const float4*)xs[2];
    const float4* x3p = (const float4*)xs[3];
    float acc0 = 0.f, acc1 = 0.f, acc2 = 0.f, acc3 = 0.f;
    #pragma unroll
    for (int i = 0; i < 8; i++) {
        const int o = i * 32 + lane;
        const float4 wvv = wv[i];
        float4 v;
        v = x0p[o];
        acc0 = fmaf(wvv.x, v.x, fmaf(wvv.y, v.y, fmaf(wvv.z, v.z, fmaf(wvv.w, v.w, acc0))));
        v = x1p[o];
        acc1 = fmaf(wvv.x, v.x, fmaf(wvv.y, v.y, fmaf(wvv.z, v.z, fmaf(wvv.w, v.w, acc1))));
        v = x2p[o];
        acc2 = fmaf(wvv.x, v.x, fmaf(wvv.y, v.y, fmaf(wvv.z, v.z, fmaf(wvv.w, v.w, acc2))));
        v = x3p[o];
        acc3 = fmaf(wvv.x, v.x, fmaf(wvv.y, v.y, fmaf(wvv.z, v.z, fmaf(wvv.w, v.w, acc3))));
    }
    #pragma unroll
    for (int o = 16; o; o >>= 1) {
        acc0 += __shfl_xor_sync(0xffffffffu, acc0, o);
        acc1 += __shfl_xor_sync(0xffffffffu, acc1, o);
        acc2 += __shfl_xor_sync(0xffffffffu, acc2, o);
        acc3 += __shfl_xor_sync(0xffffffffu, acc3, o);
    }

    if (lane < 4) {
        float dot = (lane == 0) ? acc0 : (lane == 1) ? acc1
                  : (lane == 2) ? acc2 : acc3;
        const int idx = (b0 + lane) * NN + h;
        float m = BETA * mem_in[idx] + dot;
        float s = (m > 1.0f) ? 1.0f : 0.0f;
        m -= s;
        mem_out[idx] = m;
        g_spk0[idx] = s;

        float pv  = ps0[idx];
        float u   = PI_F * (m - 1.0f);
        float sur = 1.0f / (PI_F * (1.0f + u * u));
        g_a0[idx] = ((float)(*bf_ptr)) * pv * sur;

        redc[w][lane][0] = s * pv;
        redc[w][lane][1] = s;
    }
    __syncthreads();
    if (tid < 8) {
        const int bb = tid >> 1, comp = tid & 1;
        float sum = 0.f;
        #pragma unroll
        for (int ww = 0; ww < 8; ww++) sum += redc[ww][bb][comp];
        g_part[((b0 + bb) * 128 + ht) * 2 + comp] = sum;
    }
}

// ---------------------------------------------------------------------------
// K2 phase pieces (forceinline) — identical work to R12, reordered per block.
// ---------------------------------------------------------------------------
__device__ __forceinline__ void k2_store_dw0(
    float* __restrict__ dW0, const float* __restrict__ a0sh,
    int b0, int ht, int tid)
{
    #pragma unroll
    for (int bb = 0; bb < 4; bb++) {
        const float2* t0 = (const float2*)(g_t0 + (size_t)(b0 + bb) * NN);
        const float2 t0A = __ldg(t0 + tid);
        const float2 t0B = __ldg(t0 + tid + 256);
        float* brow = dW0 + (size_t)(b0 + bb) * NN * NN + (size_t)(ht * 8) * NN;
        #pragma unroll
        for (int w2 = 0; w2 < 8; w2++) {
            const float av = a0sh[w2 * 4 + bb];
            float* row = brow + (size_t)w2 * NN;
            float2 v0, v1;
            v0.x = av * t0A.x; v0.y = av * t0A.y;
            v1.x = av * t0B.x; v1.y = av * t0B.y;
            __stcs((float2*)row + tid,       v0);
            __stcs((float2*)row + tid + 256, v1);
        }
    }
}

__device__ __forceinline__ void k2_gemm(
    const float4 wv[8], const float (*xs)[NN], int lane,
    float& acc0, float& acc1, float& acc2, float& acc3)
{
    const float4* x0p = (const float4*)xs[0];
    const float4* x1p = (const float4*)xs[1];
    const float4* x2p = (const float4*)xs[2];
    const float4* x3p = (const float4*)xs[3];
    #pragma unroll
    for (int i = 0; i < 8; i++) {
        const int o = i * 32 + lane;
        const float4 wvv = wv[i];
        float4 v;
        v = x0p[o];
        acc0 = fmaf(wvv.x, v.x, fmaf(wvv.y, v.y, fmaf(wvv.z, v.z, fmaf(wvv.w, v.w, acc0))));
        v = x1p[o];
        acc1 = fmaf(wvv.x, v.x, fmaf(wvv.y, v.y, fmaf(wvv.z, v.z, fmaf(wvv.w, v.w, acc1))));
        v = x2p[o];
        acc2 = fmaf(wvv.x, v.x, fmaf(wvv.y, v.y, fmaf(wvv.z, v.z, fmaf(wvv.w, v.w, acc2))));
        v = x3p[o];
        acc3 = fmaf(wvv.x, v.x, fmaf(wvv.y, v.y, fmaf(wvv.z, v.z, fmaf(wvv.w, v.w, acc3))));
    }
    #pragma unroll
    for (int o = 16; o; o >>= 1) {
        acc0 += __shfl_xor_sync(0xffffffffu, acc0, o);
        acc1 += __shfl_xor_sync(0xffffffffu, acc1, o);
        acc2 += __shfl_xor_sync(0xffffffffu, acc2, o);
        acc3 += __shfl_xor_sync(0xffffffffu, acc3, o);
    }
}

// ---------------------------------------------------------------------------
// K2: uniform fused blocks with PHASE STAGGERING by cid parity:
//   even cid: storeDW0 -> GEMM -> epi -> storeDW1
//   odd  cid: GEMM -> epi -> storeDW1 -> storeDW0
// so at any instant ~half the chip is in a pure-store phase.
// ---------------------------------------------------------------------------
__global__ void __launch_bounds__(256)
k2_mid(const float* __restrict__ W1, const float* __restrict__ mem1,
       const float* __restrict__ ps1, const float* __restrict__ it1,
       const int* __restrict__ bf_ptr,
       float* __restrict__ mem1_o, float* __restrict__ spk1_o,
       float* __restrict__ dW0, float* __restrict__ dW1)
{
    __shared__ __align__(16) float xs[4][NN];   // spk0 rows
    __shared__ __align__(16) float ts[4][NN];   // trace1 rows
    __shared__ float a0sh[32];                  // a0[w2*4+bb]
    __shared__ float a1sh[8][4];
    __shared__ float redc[8][4][2];

    const int tid = threadIdx.x;
    const int w   = tid >> 5, lane = tid & 31;
    const int cid = blockIdx.x;
    const int ht  = cid >> 3;
    const int b0  = (cid & 7) * 4;

    // ---- stage: spk0 + trace1 -> smem ; a0 tile -> smem ----
    {
        const float4* xp = (const float4*)(g_spk0 + (size_t)b0 * NN);
        const float4* ip = (const float4*)(it1    + (size_t)b0 * NN);
        float4 xv[4], iv[4];
        #pragma unroll
        for (int r = 0; r < 4; r++) {
            xv[r] = __ldg(xp + tid + 256 * r);
            iv[r] = __ldg(ip + tid + 256 * r);
        }
        if (tid < 32)
            a0sh[tid] = g_a0[(size_t)(b0 + (tid & 3)) * NN + ht * 8 + (tid >> 2)];
        float4* xsp = (float4*)xs;
        float4* tsp = (float4*)ts;
        #pragma unroll
        for (int r = 0; r < 4; r++) {
            xsp[tid + 256 * r] = xv[r];
            float4 t;
            t.x = fmaf(BETA, iv[r].x, xv[r].x);
            t.y = fmaf(BETA, iv[r].y, xv[r].y);
            t.z = fmaf(BETA, iv[r].z, xv[r].z);
            t.w = fmaf(BETA, iv[r].w, xv[r].w);
            tsp[tid + 256 * r] = t;
        }
    }
    __syncthreads();

    // ---- W1 front-batch ----
    const int h = ht * 8 + w;
    const float4* wr = (const float4*)(W1 + (size_t)h * NN);
    float4 wv[8];
    #pragma unroll
    for (int i = 0; i < 8; i++) wv[i] = __ldg(wr + i * 32 + lane);

    float acc0 = 0.f, acc1 = 0.f, acc2 = 0.f, acc3 = 0.f;
    const bool even = (cid & 1) == 0;

    if (even) {
        k2_store_dw0(dW0, a0sh, b0, ht, tid);          // store first
        k2_gemm(wv, xs, lane, acc0, acc1, acc2, acc3); // then compute
    } else {
        k2_gemm(wv, xs, lane, acc0, acc1, acc2, acc3); // compute first
    }

    // ---- LIF epilogue ----
    if (lane < 4) {
        float dot = (lane == 0) ? acc0 : (lane == 1) ? acc1
                  : (lane == 2) ? acc2 : acc3;
        const int idx = (b0 + lane) * NN + h;
        float m = BETA * mem1[idx] + dot;
        float s = (m > 1.0f) ? 1.0f : 0.0f;
        m -= s;
        mem1_o[idx] = m;
        spk1_o[idx] = s;

        float pv  = ps1[idx];
        float u   = PI_F * (m - 1.0f);
        float sur = 1.0f / (PI_F * (1.0f + u * u));
        a1sh[w][lane] = ((float)(*bf_ptr)) * pv * sur;

        redc[w][lane][0] = s * pv;
        redc[w][lane][1] = s;
    }
    __syncthreads();

    if (tid < 8) {
        const int bb = tid >> 1, comp = tid & 1;
        float sum = 0.f;
        #pragma unroll
        for (int ww = 0; ww < 8; ww++) sum += redc[ww][bb][comp];
        g_part[BB * 128 * 2 + ((b0 + bb) * 128 + ht) * 2 + comp] = sum;
    }

    // ---- dW1 store ----
    #pragma unroll
    for (int bb = 0; bb < 4; bb++) {
        const float2 tA = *((const float2*)ts[bb] + tid);
        const float2 tB = *((const float2*)ts[bb] + tid + 256);
        float* brow = dW1 + (size_t)(b0 + bb) * NN * NN + (size_t)(ht * 8) * NN;
        #pragma unroll
        for (int w2 = 0; w2 < 8; w2++) {
            const float av = a1sh[w2][bb];
            float* row = brow + (size_t)w2 * NN;
            float2 v0, v1;
            v0.x = av * tA.x; v0.y = av * tA.y;
            v1.x = av * tB.x; v1.y = av * tB.y;
            __stcs((float2*)row + tid,       v0);
            __stcs((float2*)row + tid + 256, v1);
        }
    }

    if (!even) {
        k2_store_dw0(dW0, a0sh, b0, ht, tid);          // store dW0 last
    }
}

// ---------------------------------------------------------------------------
// K3: loss finalize, 1 block 256 threads.
// ---------------------------------------------------------------------------
__global__ void __launch_bounds__(256)
k3_loss(const int* __restrict__ bf, float* __restrict__ loss_o)
{
    __shared__ float vsh[64];
    const int tid  = threadIdx.x;
    const int pair = tid >> 2;            // 0..63 = (l,b)
    const int seg  = tid & 3;
    const int l = pair >> 5, b = pair & 31;
    const float* part = g_part + l * (BB * 128 * 2) + b * 128 * 2;
    float s1 = 0.f, s2 = 0.f;
    for (int h2 = seg * 32; h2 < seg * 32 + 32; h2++) {
        s1 += part[h2 * 2 + 0];
        s2 += part[h2 * 2 + 1];
    }
    #pragma unroll
    for (int o = 2; o; o >>= 1) {
        s1 += __shfl_down_sync(0xffffffffu, s1, o);
        s2 += __shfl_down_sync(0xffffffffu, s2, o);
    }
    if (seg == 0) vsh[pair] = s1 - g_mean[l * BB + b] * s2;
    __syncthreads();
    if (tid < 2) {
        float tot = 0.f;
        #pragma unroll
        for (int i = 0; i < BB; i++) tot += vsh[tid * BB + i];
        loss_o[tid] = -((float)(*bf)) * tot * (1.0f / (float)BB);
    }
}

extern "C" void kernel_launch(void* const* d_in, const int* in_sizes, int n_in,
                              void* d_out, int out_size) {
    (void)in_sizes; (void)n_in; (void)out_size;
    const float* inp  = (const float*)d_in[0];
    const float* W0   = (const float*)d_in[1];
    const float* W1   = (const float*)d_in[2];
    const float* mem0 = (const float*)d_in[3];
    const float* mem1 = (const float*)d_in[4];
    const float* ps0  = (const float*)d_in[5];
    const float* ps1  = (const float*)d_in[6];
    const float* it0  = (const float*)d_in[7];
    const float* it1  = (const float*)d_in[8];
    const int*   bf   = (const int*)d_in[9];

    float* out    = (float*)d_out;
    float* spk1_o = out;                               // (32,1024)
    float* mem0_o = out + BB * NN;                     // (32,1024)
    float* mem1_o = out + 2 * BB * NN;                 // (32,1024)
    float* loss_o = out + 3 * BB * NN;                 // (2,)
    float* dW0_o  = out + 3 * BB * NN + 2;             // (32,1024,1024)
    float* dW1_o  = dW0_o + (size_t)BB * NN * NN;      // (32,1024,1024)

    k1_compute0<<<1026, 256>>>(inp, W0, mem0, ps0, ps1, it0, bf, mem0_o);
    k2_mid<<<1024, 256>>>(W1, mem1, ps1, it1, bf,
                          mem1_o, spk1_o, dW0_o, dW1_o);
    k3_loss<<<1, 256>>>(bf, loss_o);
}

// round 17
// speedup vs baseline: 1.1958x; 1.0620x over previous
#include <cuda_runtime.h>

#define BETA  0.95f
#define PI_F  3.141592653589793f
#define BB    32
#define NN    1024

// Scratch (device globals — no allocation allowed)
__device__ float g_spk0[BB * NN];
__device__ float g_a0[BB * NN];
__device__ float g_t0[BB * NN];
__device__ float g_a1[BB * NN];
__device__ float g_t1[BB * NN];
__device__ float g_mean[2 * BB];
__device__ float g_part[2 * BB * 128 * 2];   // per-(layer,b,htile) {spk*prev, spk}

// ---------------------------------------------------------------------------
// Shared layer-compute body: GEMM tile (8 h x 4 b, 256 thr) -> LIF -> scratch.
// ---------------------------------------------------------------------------
__device__ __forceinline__ void layer_compute(
    const float* __restrict__ x,
    const float* __restrict__ W,
    const float* __restrict__ mem_in,
    const float* __restrict__ prev,
    const float* __restrict__ itr,
    const int*   __restrict__ bf_ptr,
    float* __restrict__ mem_out,
    float* __restrict__ spk_out,
    float* __restrict__ a_out,
    float* __restrict__ t_out,
    float* __restrict__ part,
    int cid)
{
    __shared__ __align__(16) float xs[4][NN];
    __shared__ float redc[8][4][2];

    const int tid = threadIdx.x;
    const int w   = tid >> 5, lane = tid & 31;
    const int ht  = cid >> 3;
    const int b0  = (cid & 7) * 4;

    {
        const float4* xp = (const float4*)(x + (size_t)b0 * NN);
        float4 xv[4];
        #pragma unroll
        for (int r = 0; r < 4; r++) xv[r] = __ldg(xp + tid + 256 * r);
        float4* xsp = (float4*)xs;
        #pragma unroll
        for (int r = 0; r < 4; r++) xsp[tid + 256 * r] = xv[r];
        if (ht == 0) {
            const float4* ip = (const float4*)(itr + (size_t)b0 * NN);
            float4* tp = (float4*)(t_out + (size_t)b0 * NN);
            #pragma unroll
            for (int r = 0; r < 4; r++) {
                float4 iv = __ldg(ip + tid + 256 * r);
                float4 t;
                t.x = fmaf(BETA, iv.x, xv[r].x);
                t.y = fmaf(BETA, iv.y, xv[r].y);
                t.z = fmaf(BETA, iv.z, xv[r].z);
                t.w = fmaf(BETA, iv.w, xv[r].w);
                tp[tid + 256 * r] = t;
            }
        }
    }
    __syncthreads();

    const int h = ht * 8 + w;
    const float4* wr = (const float4*)(W + (size_t)h * NN);
    float4 wv[8];
    #pragma unroll
    for (int i = 0; i < 8; i++) wv[i] = __ldg(wr + i * 32 + lane);

    const float4* x0p = (const float4*)xs[0];
    const float4* x1p = (const float4*)xs[1];
    const float4* x2p = (const float4*)xs[2];
    const float4* x3p = (const float4*)xs[3];
    float acc0 = 0.f, acc1 = 0.f, acc2 = 0.f, acc3 = 0.f;
    #pragma unroll
    for (int i = 0; i < 8; i++) {
        const int o = i * 32 + lane;
        const float4 wvv = wv[i];
        float4 v;
        v = x0p[o];
        acc0 = fmaf(wvv.x, v.x, fmaf(wvv.y, v.y, fmaf(wvv.z, v.z, fmaf(wvv.w, v.w, acc0))));
        v = x1p[o];
        acc1 = fmaf(wvv.x, v.x, fmaf(wvv.y, v.y, fmaf(wvv.z, v.z, fmaf(wvv.w, v.w, acc1))));
        v = x2p[o];
        acc2 = fmaf(wvv.x, v.x, fmaf(wvv.y, v.y, fmaf(wvv.z, v.z, fmaf(wvv.w, v.w, acc2))));
        v = x3p[o];
        acc3 = fmaf(wvv.x, v.x, fmaf(wvv.y, v.y, fmaf(wvv.z, v.z, fmaf(wvv.w, v.w, acc3))));
    }
    #pragma unroll
    for (int o = 16; o; o >>= 1) {
        acc0 += __shfl_xor_sync(0xffffffffu, acc0, o);
        acc1 += __shfl_xor_sync(0xffffffffu, acc1, o);
        acc2 += __shfl_xor_sync(0xffffffffu, acc2, o);
        acc3 += __shfl_xor_sync(0xffffffffu, acc3, o);
    }

    if (lane < 4) {
        float dot = (lane == 0) ? acc0 : (lane == 1) ? acc1
                  : (lane == 2) ? acc2 : acc3;
        const int idx = (b0 + lane) * NN + h;
        float m = BETA * mem_in[idx] + dot;
        float s = (m > 1.0f) ? 1.0f : 0.0f;
        m -= s;
        mem_out[idx] = m;
        spk_out[idx] = s;

        float pv  = prev[idx];
        float u   = PI_F * (m - 1.0f);
        float sur = 1.0f / (PI_F * (1.0f + u * u));
        a_out[idx] = ((float)(*bf_ptr)) * pv * sur;

        redc[w][lane][0] = s * pv;
        redc[w][lane][1] = s;
    }
    __syncthreads();
    if (tid < 8) {
        const int bb = tid >> 1, comp = tid & 1;
        float sum = 0.f;
        #pragma unroll
        for (int ww = 0; ww < 8; ww++) sum += redc[ww][bb][comp];
        part[((b0 + bb) * 128 + ht) * 2 + comp] = sum;
    }
}

// ---------------------------------------------------------------------------
// K1: layer-0 compute (1024 blocks) + row means (2 blocks).
// ---------------------------------------------------------------------------
__global__ void __launch_bounds__(256)
k1_compute0(const float* __restrict__ inp, const float* __restrict__ W0,
            const float* __restrict__ mem0, const float* __restrict__ ps0,
            const float* __restrict__ ps1, const float* __restrict__ it0,
            const int* __restrict__ bf, float* __restrict__ mem0_o)
{
    const int bid = blockIdx.x;
    if (bid < 1024) {
        layer_compute(inp, W0, mem0, ps0, it0, bf,
                      mem0_o, g_spk0, g_a0, g_t0, g_part, bid);
        return;
    }
    // row means of ps0 / ps1
    const int tid = threadIdx.x;
    const int w = tid >> 5, lane = tid & 31;
    const int l = bid - 1024;
    const float* prev = l ? ps1 : ps0;
    #pragma unroll
    for (int r = 0; r < 4; r++) {
        const int b = w * 4 + r;
        const float* row = prev + (size_t)b * NN;
        float s = 0.f;
        #pragma unroll
        for (int k = 0; k < NN / 32; k++) s += row[lane + 32 * k];
        #pragma unroll
        for (int o = 16; o; o >>= 1) s += __shfl_down_sync(0xffffffffu, s, o);
        if (lane == 0) g_mean[l * BB + b] = s * (1.0f / NN);
    }
}

// ---------------------------------------------------------------------------
// K2: blocks 0..511 pure dW0 store (64-row tiles, 256 thr);
//     blocks 512..1535 PURE layer-1 compute (a1/t1 to scratch, no dW store).
// ---------------------------------------------------------------------------
__global__ void __launch_bounds__(256)
k2_mid(const float* __restrict__ W1, const float* __restrict__ mem1,
       const float* __restrict__ ps1, const float* __restrict__ it1,
       const int* __restrict__ bf,
       float* __restrict__ mem1_o, float* __restrict__ spk1_o,
       float* __restrict__ dW0)
{
    const int bid = blockIdx.x;
    const int tid = threadIdx.x;

    if (bid < 512) {                        // ---- pure dW0 store tile ----
        __shared__ float as_[64];
        const int b    = bid >> 4;
        const int tile = bid & 15;
        const float*  a = g_a0 + b * NN + tile * 64;
        const float2* t = (const float2*)(g_t0 + b * NN);
        if (tid < 64) as_[tid] = a[tid];
        const float2 t0 = __ldg(t + tid);
        const float2 t1 = __ldg(t + tid + 256);
        __syncthreads();

        float* dst = dW0 + (size_t)b * NN * NN + (size_t)tile * 64 * NN;
        #pragma unroll 4
        for (int i = 0; i < 64; i++) {
            const float av = as_[i];
            float* row = dst + (size_t)i * NN;
            float2 v0, v1;
            v0.x = av * t0.x; v0.y = av * t0.y;
            v1.x = av * t1.x; v1.y = av * t1.y;
            __stcs((float2*)row + tid,       v0);
            __stcs((float2*)row + tid + 256, v1);
        }
        return;
    }

    layer_compute(g_spk0, W1, mem1, ps1, it1, bf,
                  mem1_o, spk1_o, g_a1, g_t1,
                  g_part + BB * 128 * 2, bid - 512);
}

// ---------------------------------------------------------------------------
// K3: pure dW1 store wave — 1024 blocks x 128 thr, 32-row tiles (the R6
// config that hit ~7.4 TB/s) + 2 loss blocks hidden in the wave.
// ---------------------------------------------------------------------------
__global__ void __launch_bounds__(128)
k3_tail(float* __restrict__ dW1,
        const int* __restrict__ bf, float* __restrict__ loss_o)
{
    const int bid = blockIdx.x;
    const int tid = threadIdx.x;          // 128

    if (bid < 1024) {                     // ---- dW1 store tile (32 rows) ----
        __shared__ float as_[32];
        const int b    = bid >> 5;
        const int tile = bid & 31;
        const float*  a = g_a1 + b * NN + tile * 32;
        const float2* t = (const float2*)(g_t1 + b * NN);
        if (tid < 32) as_[tid] = a[tid];
        float2 tv[4];
        #pragma unroll
        for (int j = 0; j < 4; j++) tv[j] = __ldg(t + tid + 128 * j);
        __syncthreads();

        float* dst = dW1 + (size_t)b * NN * NN + (size_t)tile * 32 * NN;
        #pragma unroll 4
        for (int i = 0; i < 32; i++) {
            const float av = as_[i];
            float* row = dst + (size_t)i * NN;
            #pragma unroll
            for (int j = 0; j < 4; j++) {
                float2 v;
                v.x = av * tv[j].x;
                v.y = av * tv[j].y;
                __stcs((float2*)row + tid + 128 * j, v);
            }
        }
        return;
    }

    // ---- loss finalize for layer l (128 threads) ----
    {
        __shared__ float vsh[BB];
        const int l = bid - 1024;
        const float* part = g_part + l * (BB * 128 * 2);
        const int b = tid >> 2, seg = tid & 3;    // 4 threads per b
        float s1 = 0.f, s2 = 0.f;
        for (int h2 = seg * 32; h2 < seg * 32 + 32; h2++) {
            s1 += part[(b * 128 + h2) * 2 + 0];
            s2 += part[(b * 128 + h2) * 2 + 1];
        }
        #pragma unroll
        for (int o = 2; o; o >>= 1) {
            s1 += __shfl_down_sync(0xffffffffu, s1, o);
            s2 += __shfl_down_sync(0xffffffffu, s2, o);
        }
        if (seg == 0) vsh[b] = s1 - g_mean[l * BB + b] * s2;
        __syncthreads();
        if (tid == 0) {
            float tot = 0.f;
            #pragma unroll
            for (int i = 0; i < BB; i++) tot += vsh[i];
            loss_o[l] = -((float)(*bf)) * tot * (1.0f / (float)BB);
        }
    }
}

extern "C" void kernel_launch(void* const* d_in, const int* in_sizes, int n_in,
                              void* d_out, int out_size) {
    (void)in_sizes; (void)n_in; (void)out_size;
    const float* inp  = (const float*)d_in[0];
    const float* W0   = (const float*)d_in[1];
    const float* W1   = (const float*)d_in[2];
    const float* mem0 = (const float*)d_in[3];
    const float* mem1 = (const float*)d_in[4];
    const float* ps0  = (const float*)d_in[5];
    const float* ps1  = (const float*)d_in[6];
    const float* it0  = (const float*)d_in[7];
    const float* it1  = (const float*)d_in[8];
    const int*   bf   = (const int*)d_in[9];

    float* out    = (float*)d_out;
    float* spk1_o = out;                               // (32,1024)
    float* mem0_o = out + BB * NN;                     // (32,1024)
    float* mem1_o = out + 2 * BB * NN;                 // (32,1024)
    float* loss_o = out + 3 * BB * NN;                 // (2,)
    float* dW0_o  = out + 3 * BB * NN + 2;             // (32,1024,1024)
    float* dW1_o  = dW0_o + (size_t)BB * NN * NN;      // (32,1024,1024)

    k1_compute0<<<1026, 256>>>(inp, W0, mem0, ps0, ps1, it0, bf, mem0_o);
    k2_mid<<<1536, 256>>>(W1, mem1, ps1, it1, bf, mem1_o, spk1_o, dW0_o);
    k3_tail<<<1026, 128>>>(dW1_o, bf, loss_o);
}